// round 10
// baseline (speedup 1.0000x reference)
#include <cuda_runtime.h>
#include <cstdint>

#define S_LEN 1024
#define DM 256
#define NH 8
#define DU 32
#define NT 16               // S_LEN / 64
#define TEMPC 0.078125f     // TEMP / (2*DU) = 5/64

// ---------------- scratch (no allocations allowed) ----------------
__device__ float g_Q[S_LEN * DM];
__device__ float g_K[S_LEN * DM];
__device__ float g_V[S_LEN * DM];
__device__ float g_O[S_LEN * DM];
__device__ float g_sumK[NH * S_LEN];
__device__ float g_pnum[NT * NH * S_LEN * DU];   // [jt][h][i][d]
__device__ float g_pden[NT * NH * S_LEN];        // [jt][h][i]
__device__ float g_Pp[4 * S_LEN * DM];           // proj k-split partials

// ---------------- packed f32x2 helpers ----------------
__device__ __forceinline__ uint64_t f32x2_add(uint64_t a, uint64_t b) {
    uint64_t d; asm("add.rn.f32x2 %0, %1, %2;" : "=l"(d) : "l"(a), "l"(b)); return d;
}
__device__ __forceinline__ uint64_t f32x2_fma(uint64_t a, uint64_t b, uint64_t c) {
    uint64_t d; asm("fma.rn.f32x2 %0, %1, %2, %3;" : "=l"(d) : "l"(a), "l"(b), "l"(c)); return d;
}
__device__ __forceinline__ uint64_t f32x2_pack(float x, float y) {
    uint64_t d; asm("mov.b64 %0, {%1, %2};" : "=l"(d) : "f"(x), "f"(y)); return d;
}
__device__ __forceinline__ float2 f32x2_unpack(uint64_t a) {
    float2 r; asm("mov.b64 {%0, %1}, %2;" : "=f"(r.x), "=f"(r.y) : "l"(a)); return r;
}

// ---------------- 64x64-tile FFMA2 GEMM, 256 threads, double-buffered -----
// C = act( A[S_LEN,DM] @ W[DM,DM] + b ).  Per-thread 4m x 4n (accum as n-pairs).
// A tile stored DUPLICATED (float2{a,a}) -> inner loop has zero MOV packing:
//   per k: 4x LDS.64 (A, broadcast) + 1x LDS.128 (W) + 8x FFMA2.
// SUMK: emit per-row per-head sums of activated outputs (n-halves are heads).
// PARTIAL: no bias, raw partial store (k-split).
template<bool SIG, bool SUMK, bool PARTIAL>
__device__ __forceinline__ void gemm64(const float* __restrict__ A,
                                       const float* __restrict__ W,
                                       const float* __restrict__ b,
                                       float* __restrict__ C,
                                       float* __restrict__ sumk,
                                       int bm, int bn, int k0base, int nchunks)
{
    __shared__ __align__(16) float2 A2[2][32][64];  // [buf][k][m] duplicated
    __shared__ __align__(16) float  Ws[2][32][64];  // [buf][k][n]
    __shared__ float ssum[64][16];

    const int tid = threadIdx.x;                    // 0..255
    // warp covers 4 ty x 8 tx  (A: 4 distinct addrs/warp, W: 8 distinct)
    const int tx = ((tid >> 5) & 1) * 8 + (tid & 7);    // 0..15, n = tx*4
    const int ty = (tid >> 6) * 4 + ((tid >> 3) & 3);   // 0..15, m = ty*4

    uint64_t c2[4][2];     // [m][n-pair]
#pragma unroll
    for (int m = 0; m < 4; m++) { c2[m][0] = 0; c2[m][1] = 0; }

    // global-load assignments (per chunk: A 64r x 32k, W 32k x 64n; 8 floats each)
    const int ar = tid >> 2;            // 0..63
    const int ak = (tid & 3) << 3;      // 0,8,16,24
    const int wk = tid >> 3;            // 0..31
    const int wn = (tid & 7) << 3;      // 0,8,..,56

    const float* Ag = &A[(bm * 64 + ar) * DM + k0base + ak];
    const float* Wg = &W[(k0base + wk) * DM + bn * 64 + wn];

    // preload chunk 0
    {
        float4 a0 = *(const float4*)(Ag);
        float4 a1 = *(const float4*)(Ag + 4);
        float4 w0 = *(const float4*)(Wg);
        float4 w1 = *(const float4*)(Wg + 4);
        A2[0][ak + 0][ar] = make_float2(a0.x, a0.x);
        A2[0][ak + 1][ar] = make_float2(a0.y, a0.y);
        A2[0][ak + 2][ar] = make_float2(a0.z, a0.z);
        A2[0][ak + 3][ar] = make_float2(a0.w, a0.w);
        A2[0][ak + 4][ar] = make_float2(a1.x, a1.x);
        A2[0][ak + 5][ar] = make_float2(a1.y, a1.y);
        A2[0][ak + 6][ar] = make_float2(a1.z, a1.z);
        A2[0][ak + 7][ar] = make_float2(a1.w, a1.w);
        *(float4*)&Ws[0][wk][wn]     = w0;
        *(float4*)&Ws[0][wk][wn + 4] = w1;
    }
    __syncthreads();

    for (int c = 0; c < nchunks; c++) {
        const int cur = c & 1;
        float4 a0, a1, w0, w1;
        const bool more = (c + 1 < nchunks);
        if (more) {   // prefetch next chunk into regs (overlaps compute)
            const float* Agn = Ag + (c + 1) * 32;
            const float* Wgn = Wg + (size_t)(c + 1) * 32 * DM;
            a0 = *(const float4*)(Agn);
            a1 = *(const float4*)(Agn + 4);
            w0 = *(const float4*)(Wgn);
            w1 = *(const float4*)(Wgn + 4);
        }
#pragma unroll 16
        for (int k = 0; k < 32; k++) {
            uint64_t am0 = *(const uint64_t*)&A2[cur][k][ty * 4 + 0];
            uint64_t am1 = *(const uint64_t*)&A2[cur][k][ty * 4 + 1];
            uint64_t am2 = *(const uint64_t*)&A2[cur][k][ty * 4 + 2];
            uint64_t am3 = *(const uint64_t*)&A2[cur][k][ty * 4 + 3];
            ulonglong2 wp = *(const ulonglong2*)&Ws[cur][k][tx * 4];
            c2[0][0] = f32x2_fma(am0, wp.x, c2[0][0]);
            c2[0][1] = f32x2_fma(am0, wp.y, c2[0][1]);
            c2[1][0] = f32x2_fma(am1, wp.x, c2[1][0]);
            c2[1][1] = f32x2_fma(am1, wp.y, c2[1][1]);
            c2[2][0] = f32x2_fma(am2, wp.x, c2[2][0]);
            c2[2][1] = f32x2_fma(am2, wp.y, c2[2][1]);
            c2[3][0] = f32x2_fma(am3, wp.x, c2[3][0]);
            c2[3][1] = f32x2_fma(am3, wp.y, c2[3][1]);
        }
        if (more) {
            const int nxt = 1 - cur;
            A2[nxt][ak + 0][ar] = make_float2(a0.x, a0.x);
            A2[nxt][ak + 1][ar] = make_float2(a0.y, a0.y);
            A2[nxt][ak + 2][ar] = make_float2(a0.z, a0.z);
            A2[nxt][ak + 3][ar] = make_float2(a0.w, a0.w);
            A2[nxt][ak + 4][ar] = make_float2(a1.x, a1.x);
            A2[nxt][ak + 5][ar] = make_float2(a1.y, a1.y);
            A2[nxt][ak + 6][ar] = make_float2(a1.z, a1.z);
            A2[nxt][ak + 7][ar] = make_float2(a1.w, a1.w);
            *(float4*)&Ws[nxt][wk][wn]     = w0;
            *(float4*)&Ws[nxt][wk][wn + 4] = w1;
            __syncthreads();
        }
    }

    float bb[4] = {0.f, 0.f, 0.f, 0.f};
    if (!PARTIAL) {
        float4 bv = *(const float4*)&b[bn * 64 + tx * 4];
        bb[0] = bv.x; bb[1] = bv.y; bb[2] = bv.z; bb[3] = bv.w;
    }
    float rs[4];
#pragma unroll
    for (int m = 0; m < 4; m++) {
        float2 p0 = f32x2_unpack(c2[m][0]);
        float2 p1 = f32x2_unpack(c2[m][1]);
        float t[4] = {p0.x + bb[0], p0.y + bb[1], p1.x + bb[2], p1.y + bb[3]};
        if (SIG) {
#pragma unroll
            for (int n = 0; n < 4; n++) t[n] = 1.0f / (1.0f + __expf(-t[n]));
        }
        if (SUMK) rs[m] = (t[0] + t[1]) + (t[2] + t[3]);
        *(float4*)&C[(bm * 64 + ty * 4 + m) * DM + bn * 64 + tx * 4] =
            make_float4(t[0], t[1], t[2], t[3]);
    }

    if (SUMK) {
        __syncthreads();
#pragma unroll
        for (int m = 0; m < 4; m++) ssum[ty * 4 + m][tx] = rs[m];
        __syncthreads();
        if (tid < 128) {
            int m = tid >> 1, half = tid & 1;
            float s = 0.f;
#pragma unroll
            for (int x = 0; x < 8; x++) s += ssum[m][half * 8 + x];
            sumk[(bn * 2 + half) * S_LEN + bm * 64 + m] = s;
        }
    }
}

__global__ __launch_bounds__(256) void qkv_kernel(const float* __restrict__ x,
                                                  const float* __restrict__ Wq, const float* __restrict__ bq,
                                                  const float* __restrict__ Wk, const float* __restrict__ bk,
                                                  const float* __restrict__ Wv, const float* __restrict__ bv)
{
    int z = blockIdx.z;
    if (z == 0)      gemm64<true,  false, false>(x, Wq, bq, g_Q, nullptr, blockIdx.x, blockIdx.y, 0, 8);
    else if (z == 1) gemm64<true,  true,  false>(x, Wk, bk, g_K, g_sumK,  blockIdx.x, blockIdx.y, 0, 8);
    else             gemm64<false, false, false>(x, Wv, bv, g_V, nullptr, blockIdx.x, blockIdx.y, 0, 8);
}

// proj: k-split 4 -> partials in g_Pp (deterministic, no atomics)
__global__ __launch_bounds__(256) void proj_kernel(const float* __restrict__ Wo)
{
    int z = blockIdx.z;
    gemm64<false, false, true>(g_O, Wo, nullptr, g_Pp + (size_t)z * S_LEN * DM,
                               nullptr, blockIdx.x, blockIdx.y, z * 64, 2);
}

__global__ __launch_bounds__(256) void combine_kernel(const float* __restrict__ bo,
                                                      float* __restrict__ out)
{
    int idx = blockIdx.x * 256 + threadIdx.x;   // 65536 float4s
    int i = idx >> 6;
    int c4 = (idx & 63) << 2;
    const size_t sp = (size_t)S_LEN * DM;
    size_t off = (size_t)i * DM + c4;
    float4 p0 = *(const float4*)&g_Pp[off];
    float4 p1 = *(const float4*)&g_Pp[sp + off];
    float4 p2 = *(const float4*)&g_Pp[2 * sp + off];
    float4 p3 = *(const float4*)&g_Pp[3 * sp + off];
    float4 bv = *(const float4*)&bo[c4];
    *(float4*)&out[off] = make_float4(((p0.x + p1.x) + (p2.x + p3.x)) + bv.x,
                                      ((p0.y + p1.y) + (p2.y + p3.y)) + bv.y,
                                      ((p0.z + p1.z) + (p2.z + p3.z)) + bv.z,
                                      ((p0.w + p1.w) + (p2.w + p3.w)) + bv.w);
}

// ---------------- attention tile kernel (packed f32x2) ----------------
// p_ij = exp( TEMPC * (sumK_j - sum_d |Q_id - K_jd|) ); row-const terms cancel.
// Grid.x enumerates the 136 lower-triangle (it,jt) tiles exactly.
__global__ __launch_bounds__(256) void attn_kernel()
{
    // decode triangular index -> (it, jt)
    int t = blockIdx.x;
    int it = (int)((sqrtf(8.0f * t + 1.0f) - 1.0f) * 0.5f);
    if ((it + 1) * (it + 2) / 2 <= t) it++;
    const int jt = t - it * (it + 1) / 2;
    const int h = blockIdx.y;

    __shared__ __align__(16) union SM {
        struct { float Kn[64][32]; float Vs[64][32]; float sK[64]; } a;
        struct { float red[4][64][33]; float redden[4][64]; } b;
    } sm;

    const int tid = threadIdx.x;
    const int ti = tid & 63;           // query row within tile
    const int tg = tid >> 6;           // 0..3, 4-way split over j

    // load K (negated) and V tiles
#pragma unroll
    for (int l = 0; l < 2; l++) {
        int f = tid + l * 256;
        int r = f >> 3;
        int c4 = (f & 7) << 2;
        float4 kv = *(const float4*)&g_K[(jt * 64 + r) * DM + h * DU + c4];
        kv.x = -kv.x; kv.y = -kv.y; kv.z = -kv.z; kv.w = -kv.w;
        *(float4*)&sm.a.Kn[r][c4] = kv;
        *(float4*)&sm.a.Vs[r][c4] = *(const float4*)&g_V[(jt * 64 + r) * DM + h * DU + c4];
    }
    if (tid < 64) sm.a.sK[tid] = g_sumK[h * S_LEN + jt * 64 + tid];

    const int ig = it * 64 + ti;
    uint64_t qp[16];
    {
        const ulonglong2* qg = (const ulonglong2*)&g_Q[ig * DM + h * DU];
#pragma unroll
        for (int c = 0; c < 8; c++) { ulonglong2 u = qg[c]; qp[2 * c] = u.x; qp[2 * c + 1] = u.y; }
    }
    __syncthreads();

    uint64_t acc[16];
#pragma unroll
    for (int c = 0; c < 16; c++) acc[c] = 0;
    float den = 0.f;
    const uint64_t AMASK = 0x7FFFFFFF7FFFFFFFULL;

    auto jbody = [&](int jl) {
        const ulonglong2* kr = (const ulonglong2*)&sm.a.Kn[jl][0];
        uint64_t s0 = 0, s1 = 0;
#pragma unroll
        for (int c = 0; c < 8; c++) {
            ulonglong2 kc = kr[c];
            uint64_t t0 = f32x2_add(qp[2 * c], kc.x) & AMASK;       // FADD2 + 2xLOP3
            uint64_t t1 = f32x2_add(qp[2 * c + 1], kc.y) & AMASK;
            s0 = f32x2_add(s0, t0);
            s1 = f32x2_add(s1, t1);
        }
        float2 u0 = f32x2_unpack(s0), u1 = f32x2_unpack(s1);
        float s = (u0.x + u0.y) + (u1.x + u1.y);
        float p = __expf(TEMPC * (sm.a.sK[jl] - s));
        den += p;
        uint64_t pp = f32x2_pack(p, p);
        const ulonglong2* vr = (const ulonglong2*)&sm.a.Vs[jl][0];
#pragma unroll
        for (int c = 0; c < 8; c++) {
            ulonglong2 vc = vr[c];
            acc[2 * c]     = f32x2_fma(pp, vc.x, acc[2 * c]);       // FFMA2
            acc[2 * c + 1] = f32x2_fma(pp, vc.y, acc[2 * c + 1]);
        }
    };

    if (it != jt) {
#pragma unroll 2
        for (int jj = 0; jj < 16; jj++) jbody((jj << 2) + tg);
    } else {
#pragma unroll 2
        for (int jj = 0; jj < 16; jj++) {
            int jl = (jj << 2) + tg;
            if (jl <= ti) jbody(jl);      // causal (diagonal tile only)
        }
    }

    __syncthreads();   // all warps done with Kn/Vs before overlay write
#pragma unroll
    for (int c = 0; c < 16; c++) {
        float2 u = f32x2_unpack(acc[c]);
        sm.b.red[tg][ti][2 * c]     = u.x;
        sm.b.red[tg][ti][2 * c + 1] = u.y;
    }
    sm.b.redden[tg][ti] = den;
    __syncthreads();

    const int i2 = tid >> 2;       // 0..63
    const int dg = tid & 3;        // 8 d's each
    const int base = dg * 8;
    const int gi = it * 64 + i2;
    float outv[8];
#pragma unroll
    for (int dd = 0; dd < 8; dd++)
        outv[dd] = (sm.b.red[0][i2][base + dd] + sm.b.red[1][i2][base + dd]) +
                   (sm.b.red[2][i2][base + dd] + sm.b.red[3][i2][base + dd]);

    float* np = &g_pnum[(((size_t)jt * NH + h) * S_LEN + gi) * DU + base];
    *(float4*)&np[0] = make_float4(outv[0], outv[1], outv[2], outv[3]);
    *(float4*)&np[4] = make_float4(outv[4], outv[5], outv[6], outv[7]);
    if (dg == 0)
        g_pden[((size_t)jt * NH + h) * S_LEN + gi] =
            (sm.b.redden[0][i2] + sm.b.redden[1][i2]) +
            (sm.b.redden[2][i2] + sm.b.redden[3][i2]);
}

// ---------------- combine partials (4-way jt split + shfl), write O --------
__global__ __launch_bounds__(256) void reduce_kernel()
{
    int gidx = blockIdx.x * 256 + threadIdx.x;          // 1,048,576 threads
    int sp = (gidx >> 3) & 3;                           // jt split 0..3
    int os = ((gidx >> 5) << 3) + (gidx & 7);           // scalar output index
    int i = os >> 8;
    int col = os & 255;
    int h = col >> 5;
    int d = col & 31;
    int it = i >> 6;
    const float* pn = &g_pnum[((size_t)h * S_LEN + i) * DU + d];
    const float* pd = &g_pden[(size_t)h * S_LEN + i];
    const size_t sj = (size_t)NH * S_LEN * DU;
    const size_t sd = (size_t)NH * S_LEN;
    float num = 0.f, den = 0.f;
#pragma unroll 4
    for (int jt = sp; jt <= it; jt += 4) {
        num += pn[(size_t)jt * sj];
        den += pd[(size_t)jt * sd];
    }
    num += __shfl_xor_sync(0xFFFFFFFFu, num, 8);
    den += __shfl_xor_sync(0xFFFFFFFFu, den, 8);
    num += __shfl_xor_sync(0xFFFFFFFFu, num, 16);
    den += __shfl_xor_sync(0xFFFFFFFFu, den, 16);
    if (sp == 0)
        g_O[i * DM + col] = num / den;
}

// ---------------- launch ----------------
extern "C" void kernel_launch(void* const* d_in, const int* in_sizes, int n_in,
                              void* d_out, int out_size)
{
    const float* x  = (const float*)d_in[0];
    const float* Wq = (const float*)d_in[1];
    const float* bq = (const float*)d_in[2];
    const float* Wk = (const float*)d_in[3];
    const float* bk = (const float*)d_in[4];
    const float* Wv = (const float*)d_in[5];
    const float* bv = (const float*)d_in[6];
    const float* Wo = (const float*)d_in[7];
    const float* bo = (const float*)d_in[8];
    float* out = (float*)d_out;

    qkv_kernel<<<dim3(16, 4, 3), 256>>>(x, Wq, bq, Wk, bk, Wv, bv);
    attn_kernel<<<dim3(136, 8), 256>>>();
    reduce_kernel<<<4096, 256>>>();
    proj_kernel<<<dim3(16, 4, 4), 256>>>(Wo);
    combine_kernel<<<256, 256>>>(bo, out);
}

// round 14
// speedup vs baseline: 1.2438x; 1.2438x over previous
#include <cuda_runtime.h>
#include <cstdint>

#define S_LEN 1024
#define DM 256
#define NH 8
#define DU 32
#define NT 16               // S_LEN / 64
#define TEMPC 0.078125f     // TEMP / (2*DU) = 5/64

// ---------------- scratch (no allocations allowed) ----------------
__device__ float g_Q[S_LEN * DM];
__device__ float g_K[S_LEN * DM];
__device__ float g_V[S_LEN * DM];
__device__ float g_O[S_LEN * DM];
__device__ float g_sumK[NH * S_LEN];
__device__ float g_pnum[NT * NH * S_LEN * DU];   // [jt][h][i][d]
__device__ float g_pden[NT * NH * S_LEN];        // [jt][h][i]
__device__ float g_part[12 * S_LEN * DM];        // k-split GEMM partials

// ---------------- packed f32x2 helpers (attn only) ----------------
__device__ __forceinline__ uint64_t f32x2_add(uint64_t a, uint64_t b) {
    uint64_t d; asm("add.rn.f32x2 %0, %1, %2;" : "=l"(d) : "l"(a), "l"(b)); return d;
}
__device__ __forceinline__ uint64_t f32x2_fma(uint64_t a, uint64_t b, uint64_t c) {
    uint64_t d; asm("fma.rn.f32x2 %0, %1, %2, %3;" : "=l"(d) : "l"(a), "l"(b), "l"(c)); return d;
}
__device__ __forceinline__ uint64_t f32x2_pack(float x, float y) {
    uint64_t d; asm("mov.b64 %0, {%1, %2};" : "=l"(d) : "f"(x), "f"(y)); return d;
}
__device__ __forceinline__ float2 f32x2_unpack(uint64_t a) {
    float2 r; asm("mov.b64 {%0, %1}, %2;" : "=f"(r.x), "=f"(r.y) : "l"(a)); return r;
}

// ---------------- 32x64-tile partial GEMM, 128 threads, 4m x 4n ----------
// R8-proven body: per k = 2x LDS.128 + 16 scalar FFMA (2 B/lane).
// No bias / activation here: epilogues live in the combine kernels.
__device__ __forceinline__ void gemm32p(const float* __restrict__ A,
                                        const float* __restrict__ W,
                                        float* __restrict__ C,
                                        int bm, int bn, int kstart, int kend)
{
    __shared__ __align__(16) float Ast[32][36];   // [k][m]
    __shared__ __align__(16) float Ws[32][64];    // [k][n]

    const int tid = threadIdx.x;      // 0..127
    const int tx = tid & 15;          // n = tx*4..+3
    const int ty = tid >> 4;          // m = ty*4..+3

    float c[4][4];
#pragma unroll
    for (int m = 0; m < 4; m++)
#pragma unroll
        for (int n = 0; n < 4; n++) c[m][n] = 0.f;

    for (int k0 = kstart; k0 < kend; k0 += 32) {
#pragma unroll
        for (int l = 0; l < 2; l++) {       // A tile 32m x 32k, transposed
            int f = tid + l * 128;
            int m = f >> 3;
            int kc = (f & 7) << 2;
            float4 v = *(const float4*)&A[(bm * 32 + m) * DM + k0 + kc];
            Ast[kc + 0][m] = v.x;
            Ast[kc + 1][m] = v.y;
            Ast[kc + 2][m] = v.z;
            Ast[kc + 3][m] = v.w;
        }
#pragma unroll
        for (int l = 0; l < 4; l++) {       // W tile 32k x 64n
            int f = tid + l * 128;
            int k = f >> 4;
            int nc = (f & 15) << 2;
            *(float4*)&Ws[k][nc] = *(const float4*)&W[(k0 + k) * DM + bn * 64 + nc];
        }
        __syncthreads();
#pragma unroll
        for (int k = 0; k < 32; k++) {
            float4 av = *(const float4*)&Ast[k][ty * 4];
            float4 wv = *(const float4*)&Ws[k][tx * 4];
            float am[4] = {av.x, av.y, av.z, av.w};
            float wn[4] = {wv.x, wv.y, wv.z, wv.w};
#pragma unroll
            for (int m = 0; m < 4; m++)
#pragma unroll
                for (int n = 0; n < 4; n++) c[m][n] += am[m] * wn[n];
        }
        __syncthreads();
    }

#pragma unroll
    for (int m = 0; m < 4; m++)
        *(float4*)&C[(bm * 32 + ty * 4 + m) * DM + bn * 64 + tx * 4] =
            make_float4(c[m][0], c[m][1], c[m][2], c[m][3]);
}

// qkv partial: z = tensor*4 + ksplit (k-split 4).  1536 blocks total.
__global__ __launch_bounds__(128) void qkv_partial(const float* __restrict__ x,
                                                   const float* __restrict__ Wq,
                                                   const float* __restrict__ Wk,
                                                   const float* __restrict__ Wv)
{
    int z = blockIdx.z;
    int t = z >> 2, ks = z & 3;
    const float* W = (t == 0) ? Wq : ((t == 1) ? Wk : Wv);
    gemm32p(x, W, g_part + (size_t)z * S_LEN * DM,
            blockIdx.x, blockIdx.y, ks * 64, ks * 64 + 64);
}

// proj partial: k-split 8.  1024 blocks.
__global__ __launch_bounds__(128) void proj_partial(const float* __restrict__ Wo)
{
    int z = blockIdx.z;
    gemm32p(g_O, Wo, g_part + (size_t)z * S_LEN * DM,
            blockIdx.x, blockIdx.y, z * 32, z * 32 + 32);
}

// combine qkv partials: bias + sigmoid(Q,K) + per-head sumK (shfl over 8 lanes)
__global__ __launch_bounds__(256) void combine_qkv(const float* __restrict__ bq,
                                                   const float* __restrict__ bk,
                                                   const float* __restrict__ bv)
{
    int idx = blockIdx.x * 256 + threadIdx.x;   // 65536, one float4 each
    int i = idx >> 6;
    int c4 = (idx & 63) << 2;
    size_t off = (size_t)i * DM + c4;
    const size_t sl = (size_t)S_LEN * DM;

    auto sum4 = [&](int base) {
        float4 a = *(const float4*)&g_part[(size_t)(base + 0) * sl + off];
        float4 b = *(const float4*)&g_part[(size_t)(base + 1) * sl + off];
        float4 c = *(const float4*)&g_part[(size_t)(base + 2) * sl + off];
        float4 d = *(const float4*)&g_part[(size_t)(base + 3) * sl + off];
        return make_float4((a.x + b.x) + (c.x + d.x), (a.y + b.y) + (c.y + d.y),
                           (a.z + b.z) + (c.z + d.z), (a.w + b.w) + (c.w + d.w));
    };

    // Q
    {
        float4 q = sum4(0);
        float4 bb = *(const float4*)&bq[c4];
        q.x = 1.0f / (1.0f + __expf(-(q.x + bb.x)));
        q.y = 1.0f / (1.0f + __expf(-(q.y + bb.y)));
        q.z = 1.0f / (1.0f + __expf(-(q.z + bb.z)));
        q.w = 1.0f / (1.0f + __expf(-(q.w + bb.w)));
        *(float4*)&g_Q[off] = q;
    }
    // K + sumK
    {
        float4 k = sum4(4);
        float4 bb = *(const float4*)&bk[c4];
        k.x = 1.0f / (1.0f + __expf(-(k.x + bb.x)));
        k.y = 1.0f / (1.0f + __expf(-(k.y + bb.y)));
        k.z = 1.0f / (1.0f + __expf(-(k.z + bb.z)));
        k.w = 1.0f / (1.0f + __expf(-(k.w + bb.w)));
        *(float4*)&g_K[off] = k;
        float s = (k.x + k.y) + (k.z + k.w);
        s += __shfl_xor_sync(0xFFFFFFFFu, s, 1);
        s += __shfl_xor_sync(0xFFFFFFFFu, s, 2);
        s += __shfl_xor_sync(0xFFFFFFFFu, s, 4);
        if ((threadIdx.x & 7) == 0) {
            int h = (idx & 63) >> 3;
            g_sumK[h * S_LEN + i] = s;
        }
    }
    // V
    {
        float4 v = sum4(8);
        float4 bb = *(const float4*)&bv[c4];
        *(float4*)&g_V[off] = make_float4(v.x + bb.x, v.y + bb.y,
                                          v.z + bb.z, v.w + bb.w);
    }
}

// combine proj partials (8) + bias -> out
__global__ __launch_bounds__(256) void combine_proj(const float* __restrict__ bo,
                                                    float* __restrict__ out)
{
    int idx = blockIdx.x * 256 + threadIdx.x;   // 65536 float4s
    int i = idx >> 6;
    int c4 = (idx & 63) << 2;
    size_t off = (size_t)i * DM + c4;
    const size_t sl = (size_t)S_LEN * DM;
    float4 s = make_float4(0.f, 0.f, 0.f, 0.f);
#pragma unroll
    for (int z = 0; z < 8; z++) {
        float4 p = *(const float4*)&g_part[(size_t)z * sl + off];
        s.x += p.x; s.y += p.y; s.z += p.z; s.w += p.w;
    }
    float4 bb = *(const float4*)&bo[c4];
    *(float4*)&out[off] = make_float4(s.x + bb.x, s.y + bb.y,
                                      s.z + bb.z, s.w + bb.w);
}

// ---------------- attention tile kernel (packed f32x2, validated R8) -------
__global__ __launch_bounds__(256) void attn_kernel()
{
    // decode triangular index -> (it, jt)
    int t = blockIdx.x;
    int it = (int)((sqrtf(8.0f * t + 1.0f) - 1.0f) * 0.5f);
    if ((it + 1) * (it + 2) / 2 <= t) it++;
    const int jt = t - it * (it + 1) / 2;
    const int h = blockIdx.y;

    __shared__ __align__(16) union SM {
        struct { float Kn[64][32]; float Vs[64][32]; float sK[64]; } a;
        struct { float red[4][64][33]; float redden[4][64]; } b;
    } sm;

    const int tid = threadIdx.x;
    const int ti = tid & 63;           // query row within tile
    const int tg = tid >> 6;           // 0..3, 4-way split over j

    // load K (negated) and V tiles
#pragma unroll
    for (int l = 0; l < 2; l++) {
        int f = tid + l * 256;
        int r = f >> 3;
        int c4 = (f & 7) << 2;
        float4 kv = *(const float4*)&g_K[(jt * 64 + r) * DM + h * DU + c4];
        kv.x = -kv.x; kv.y = -kv.y; kv.z = -kv.z; kv.w = -kv.w;
        *(float4*)&sm.a.Kn[r][c4] = kv;
        *(float4*)&sm.a.Vs[r][c4] = *(const float4*)&g_V[(jt * 64 + r) * DM + h * DU + c4];
    }
    if (tid < 64) sm.a.sK[tid] = g_sumK[h * S_LEN + jt * 64 + tid];

    const int ig = it * 64 + ti;
    uint64_t qp[16];
    {
        const ulonglong2* qg = (const ulonglong2*)&g_Q[ig * DM + h * DU];
#pragma unroll
        for (int c = 0; c < 8; c++) { ulonglong2 u = qg[c]; qp[2 * c] = u.x; qp[2 * c + 1] = u.y; }
    }
    __syncthreads();

    uint64_t acc[16];
#pragma unroll
    for (int c = 0; c < 16; c++) acc[c] = 0;
    float den = 0.f;
    const uint64_t AMASK = 0x7FFFFFFF7FFFFFFFULL;

    auto jbody = [&](int jl) {
        const ulonglong2* kr = (const ulonglong2*)&sm.a.Kn[jl][0];
        uint64_t s0 = 0, s1 = 0;
#pragma unroll
        for (int c = 0; c < 8; c++) {
            ulonglong2 kc = kr[c];
            uint64_t t0 = f32x2_add(qp[2 * c], kc.x) & AMASK;       // FADD2 + 2xLOP3
            uint64_t t1 = f32x2_add(qp[2 * c + 1], kc.y) & AMASK;
            s0 = f32x2_add(s0, t0);
            s1 = f32x2_add(s1, t1);
        }
        float2 u0 = f32x2_unpack(s0), u1 = f32x2_unpack(s1);
        float s = (u0.x + u0.y) + (u1.x + u1.y);
        float p = __expf(TEMPC * (sm.a.sK[jl] - s));
        den += p;
        uint64_t pp = f32x2_pack(p, p);
        const ulonglong2* vr = (const ulonglong2*)&sm.a.Vs[jl][0];
#pragma unroll
        for (int c = 0; c < 8; c++) {
            ulonglong2 vc = vr[c];
            acc[2 * c]     = f32x2_fma(pp, vc.x, acc[2 * c]);       // FFMA2
            acc[2 * c + 1] = f32x2_fma(pp, vc.y, acc[2 * c + 1]);
        }
    };

    if (it != jt) {
#pragma unroll 2
        for (int jj = 0; jj < 16; jj++) jbody((jj << 2) + tg);
    } else {
#pragma unroll 2
        for (int jj = 0; jj < 16; jj++) {
            int jl = (jj << 2) + tg;
            if (jl <= ti) jbody(jl);      // causal (diagonal tile only)
        }
    }

    __syncthreads();   // all warps done with Kn/Vs before overlay write
#pragma unroll
    for (int c = 0; c < 16; c++) {
        float2 u = f32x2_unpack(acc[c]);
        sm.b.red[tg][ti][2 * c]     = u.x;
        sm.b.red[tg][ti][2 * c + 1] = u.y;
    }
    sm.b.redden[tg][ti] = den;
    __syncthreads();

    const int i2 = tid >> 2;       // 0..63
    const int dg = tid & 3;        // 8 d's each
    const int base = dg * 8;
    const int gi = it * 64 + i2;
    float outv[8];
#pragma unroll
    for (int dd = 0; dd < 8; dd++)
        outv[dd] = (sm.b.red[0][i2][base + dd] + sm.b.red[1][i2][base + dd]) +
                   (sm.b.red[2][i2][base + dd] + sm.b.red[3][i2][base + dd]);

    float* np = &g_pnum[(((size_t)jt * NH + h) * S_LEN + gi) * DU + base];
    *(float4*)&np[0] = make_float4(outv[0], outv[1], outv[2], outv[3]);
    *(float4*)&np[4] = make_float4(outv[4], outv[5], outv[6], outv[7]);
    if (dg == 0)
        g_pden[((size_t)jt * NH + h) * S_LEN + gi] =
            (sm.b.redden[0][i2] + sm.b.redden[1][i2]) +
            (sm.b.redden[2][i2] + sm.b.redden[3][i2]);
}

// ---------------- combine attn partials (4-way jt split + shfl) -----------
__global__ __launch_bounds__(256) void reduce_kernel()
{
    int gidx = blockIdx.x * 256 + threadIdx.x;          // 1,048,576 threads
    int sp = (gidx >> 3) & 3;                           // jt split 0..3
    int os = ((gidx >> 5) << 3) + (gidx & 7);           // scalar output index
    int i = os >> 8;
    int col = os & 255;
    int h = col >> 5;
    int d = col & 31;
    int it = i >> 6;
    const float* pn = &g_pnum[((size_t)h * S_LEN + i) * DU + d];
    const float* pd = &g_pden[(size_t)h * S_LEN + i];
    const size_t sj = (size_t)NH * S_LEN * DU;
    const size_t sd = (size_t)NH * S_LEN;
    float num = 0.f, den = 0.f;
#pragma unroll 4
    for (int jt = sp; jt <= it; jt += 4) {
        num += pn[(size_t)jt * sj];
        den += pd[(size_t)jt * sd];
    }
    num += __shfl_xor_sync(0xFFFFFFFFu, num, 8);
    den += __shfl_xor_sync(0xFFFFFFFFu, den, 8);
    num += __shfl_xor_sync(0xFFFFFFFFu, num, 16);
    den += __shfl_xor_sync(0xFFFFFFFFu, den, 16);
    if (sp == 0)
        g_O[i * DM + col] = num / den;
}

// ---------------- launch ----------------
extern "C" void kernel_launch(void* const* d_in, const int* in_sizes, int n_in,
                              void* d_out, int out_size)
{
    const float* x  = (const float*)d_in[0];
    const float* Wq = (const float*)d_in[1];
    const float* bq = (const float*)d_in[2];
    const float* Wk = (const float*)d_in[3];
    const float* bk = (const float*)d_in[4];
    const float* Wv = (const float*)d_in[5];
    const float* bv = (const float*)d_in[6];
    const float* Wo = (const float*)d_in[7];
    const float* bo = (const float*)d_in[8];
    float* out = (float*)d_out;

    qkv_partial<<<dim3(32, 4, 12), 128>>>(x, Wq, Wk, Wv);
    combine_qkv<<<256, 256>>>(bq, bk, bv);
    attn_kernel<<<dim3(136, 8), 256>>>();
    reduce_kernel<<<4096, 256>>>();
    proj_partial<<<dim3(32, 4, 8), 128>>>(Wo);
    combine_proj<<<256, 256>>>(bo, out);
}

// round 15
// speedup vs baseline: 1.3451x; 1.0814x over previous
#include <cuda_runtime.h>
#include <cstdint>

#define S_LEN 1024
#define DM 256
#define NH 8
#define DU 32
#define NT 16               // S_LEN / 64
#define NJG 4               // j-groups (4 j-tiles each)
#define TEMPC 0.078125f     // TEMP / (2*DU) = 5/64

// ---------------- scratch (no allocations allowed) ----------------
__device__ float g_Q[S_LEN * DM];
__device__ float g_K[S_LEN * DM];
__device__ float g_V[S_LEN * DM];
__device__ float g_O[S_LEN * DM];
__device__ float g_sumK[NH * S_LEN];
__device__ float g_pnum[NJG * NH * S_LEN * DU];  // [jg][h][i][d]
__device__ float g_pden[NJG * NH * S_LEN];       // [jg][h][i]
__device__ float g_part[12 * S_LEN * DM];        // k-split GEMM partials

// (it, jg) enumeration for attn, sorted heaviest-first (w = #subtiles)
__device__ const unsigned char c_it[40] = {
    3,4,5,6,7,7,8,8,9,9,10,10,11,11,11,12,12,12,13,13,13,14,14,14,15,15,15,15,
    2,6,10,14,  1,5,9,13,  0,4,8,12};
__device__ const unsigned char c_jg[40] = {
    0,0,0,0,0,1,0,1,0,1,0,1,0,1,2,0,1,2,0,1,2,0,1,2,0,1,2,3,
    0,1,2,3,  0,1,2,3,  0,1,2,3};

// ---------------- packed f32x2 helpers ----------------
__device__ __forceinline__ uint64_t f32x2_add(uint64_t a, uint64_t b) {
    uint64_t d; asm("add.rn.f32x2 %0, %1, %2;" : "=l"(d) : "l"(a), "l"(b)); return d;
}
__device__ __forceinline__ uint64_t f32x2_fma(uint64_t a, uint64_t b, uint64_t c) {
    uint64_t d; asm("fma.rn.f32x2 %0, %1, %2, %3;" : "=l"(d) : "l"(a), "l"(b), "l"(c)); return d;
}
__device__ __forceinline__ uint64_t f32x2_pack(float x, float y) {
    uint64_t d; asm("mov.b64 %0, {%1, %2};" : "=l"(d) : "f"(x), "f"(y)); return d;
}
__device__ __forceinline__ float2 f32x2_unpack(uint64_t a) {
    float2 r; asm("mov.b64 {%0, %1}, %2;" : "=f"(r.x), "=f"(r.y) : "l"(a)); return r;
}

// ---------------- MUFU-free exp (FMA pipe): e^x = 2^n * e^r ---------------
// valid for |x| <~ 85; round via 1.5*2^23 trick, scale via exponent bits.
__device__ __forceinline__ float fast_exp(float x) {
    const float C = 12582912.0f;                 // 1.5 * 2^23
    float y = __fmaf_rn(x, 1.4426950408889634f, C);
    int ybits = __float_as_int(y);
    float nf = y - C;
    float r = __fmaf_rn(nf, -0.6931471805599453f, x);   // |r| <= 0.3466
    float scale = __int_as_float((ybits + (127 - 0x400000)) << 23);  // 2^n
    float p = 1.3888889e-3f;                     // 1/720
    p = __fmaf_rn(p, r, 8.3333333e-3f);          // 1/120
    p = __fmaf_rn(p, r, 4.1666668e-2f);          // 1/24
    p = __fmaf_rn(p, r, 1.6666667e-1f);          // 1/6
    p = __fmaf_rn(p, r, 0.5f);
    p = __fmaf_rn(p, r, 1.0f);
    p = __fmaf_rn(p, r, 1.0f);
    return p * scale;
}

// MUFU-free sigmoid: fast_exp + bit-trick reciprocal + 3 Newton steps
__device__ __forceinline__ float fast_sigmoid(float t) {
    t = fminf(fmaxf(t, -80.0f), 80.0f);
    float d = 1.0f + fast_exp(-t);
    float r = __int_as_float(0x7EF311C3 - __float_as_int(d));
    r = __fmaf_rn(__fmaf_rn(-d, r, 1.0f), r, r);
    r = __fmaf_rn(__fmaf_rn(-d, r, 1.0f), r, r);
    r = __fmaf_rn(__fmaf_rn(-d, r, 1.0f), r, r);
    return r;
}

// ---------------- 32x64-tile partial GEMM, 128 threads, 4m x 4n ----------
__device__ __forceinline__ void gemm32p(const float* __restrict__ A,
                                        const float* __restrict__ W,
                                        float* __restrict__ C,
                                        int bm, int bn, int kstart, int kend)
{
    __shared__ __align__(16) float Ast[32][36];   // [k][m]
    __shared__ __align__(16) float Ws[32][64];    // [k][n]

    const int tid = threadIdx.x;      // 0..127
    const int tx = tid & 15;          // n = tx*4..+3
    const int ty = tid >> 4;          // m = ty*4..+3

    float c[4][4];
#pragma unroll
    for (int m = 0; m < 4; m++)
#pragma unroll
        for (int n = 0; n < 4; n++) c[m][n] = 0.f;

    for (int k0 = kstart; k0 < kend; k0 += 32) {
#pragma unroll
        for (int l = 0; l < 2; l++) {       // A tile 32m x 32k, transposed
            int f = tid + l * 128;
            int m = f >> 3;
            int kc = (f & 7) << 2;
            float4 v = *(const float4*)&A[(bm * 32 + m) * DM + k0 + kc];
            Ast[kc + 0][m] = v.x;
            Ast[kc + 1][m] = v.y;
            Ast[kc + 2][m] = v.z;
            Ast[kc + 3][m] = v.w;
        }
#pragma unroll
        for (int l = 0; l < 4; l++) {       // W tile 32k x 64n
            int f = tid + l * 128;
            int k = f >> 4;
            int nc = (f & 15) << 2;
            *(float4*)&Ws[k][nc] = *(const float4*)&W[(k0 + k) * DM + bn * 64 + nc];
        }
        __syncthreads();
#pragma unroll
        for (int k = 0; k < 32; k++) {
            float4 av = *(const float4*)&Ast[k][ty * 4];
            float4 wv = *(const float4*)&Ws[k][tx * 4];
            float am[4] = {av.x, av.y, av.z, av.w};
            float wn[4] = {wv.x, wv.y, wv.z, wv.w};
#pragma unroll
            for (int m = 0; m < 4; m++)
#pragma unroll
                for (int n = 0; n < 4; n++) c[m][n] += am[m] * wn[n];
        }
        __syncthreads();
    }

#pragma unroll
    for (int m = 0; m < 4; m++)
        *(float4*)&C[(bm * 32 + ty * 4 + m) * DM + bn * 64 + tx * 4] =
            make_float4(c[m][0], c[m][1], c[m][2], c[m][3]);
}

// qkv partial: z = tensor*4 + ksplit (k-split 4).  1536 blocks total.
__global__ __launch_bounds__(128) void qkv_partial(const float* __restrict__ x,
                                                   const float* __restrict__ Wq,
                                                   const float* __restrict__ Wk,
                                                   const float* __restrict__ Wv)
{
    int z = blockIdx.z;
    int t = z >> 2, ks = z & 3;
    const float* W = (t == 0) ? Wq : ((t == 1) ? Wk : Wv);
    gemm32p(x, W, g_part + (size_t)z * S_LEN * DM,
            blockIdx.x, blockIdx.y, ks * 64, ks * 64 + 64);
}

// proj partial: k-split 8.  1024 blocks.
__global__ __launch_bounds__(128) void proj_partial(const float* __restrict__ Wo)
{
    int z = blockIdx.z;
    gemm32p(g_O, Wo, g_part + (size_t)z * S_LEN * DM,
            blockIdx.x, blockIdx.y, z * 32, z * 32 + 32);
}

// combine qkv partials: bias + sigmoid(Q,K) + per-head sumK (shfl over 8 lanes)
__global__ __launch_bounds__(256) void combine_qkv(const float* __restrict__ bq,
                                                   const float* __restrict__ bk,
                                                   const float* __restrict__ bv)
{
    int idx = blockIdx.x * 256 + threadIdx.x;   // 65536, one float4 each
    int i = idx >> 6;
    int c4 = (idx & 63) << 2;
    size_t off = (size_t)i * DM + c4;
    const size_t sl = (size_t)S_LEN * DM;

    auto sum4 = [&](int base) {
        float4 a = *(const float4*)&g_part[(size_t)(base + 0) * sl + off];
        float4 b = *(const float4*)&g_part[(size_t)(base + 1) * sl + off];
        float4 c = *(const float4*)&g_part[(size_t)(base + 2) * sl + off];
        float4 d = *(const float4*)&g_part[(size_t)(base + 3) * sl + off];
        return make_float4((a.x + b.x) + (c.x + d.x), (a.y + b.y) + (c.y + d.y),
                           (a.z + b.z) + (c.z + d.z), (a.w + b.w) + (c.w + d.w));
    };

    // Q
    {
        float4 q = sum4(0);
        float4 bb = *(const float4*)&bq[c4];
        q.x = fast_sigmoid(q.x + bb.x);
        q.y = fast_sigmoid(q.y + bb.y);
        q.z = fast_sigmoid(q.z + bb.z);
        q.w = fast_sigmoid(q.w + bb.w);
        *(float4*)&g_Q[off] = q;
    }
    // K + sumK
    {
        float4 k = sum4(4);
        float4 bb = *(const float4*)&bk[c4];
        k.x = fast_sigmoid(k.x + bb.x);
        k.y = fast_sigmoid(k.y + bb.y);
        k.z = fast_sigmoid(k.z + bb.z);
        k.w = fast_sigmoid(k.w + bb.w);
        *(float4*)&g_K[off] = k;
        float s = (k.x + k.y) + (k.z + k.w);
        s += __shfl_xor_sync(0xFFFFFFFFu, s, 1);
        s += __shfl_xor_sync(0xFFFFFFFFu, s, 2);
        s += __shfl_xor_sync(0xFFFFFFFFu, s, 4);
        if ((threadIdx.x & 7) == 0) {
            int h = (idx & 63) >> 3;
            g_sumK[h * S_LEN + i] = s;
        }
    }
    // V
    {
        float4 v = sum4(8);
        float4 bb = *(const float4*)&bv[c4];
        *(float4*)&g_V[off] = make_float4(v.x + bb.x, v.y + bb.y,
                                          v.z + bb.z, v.w + bb.w);
    }
}

// combine proj partials (8) + bias -> out
__global__ __launch_bounds__(256) void combine_proj(const float* __restrict__ bo,
                                                    float* __restrict__ out)
{
    int idx = blockIdx.x * 256 + threadIdx.x;   // 65536 float4s
    int i = idx >> 6;
    int c4 = (idx & 63) << 2;
    size_t off = (size_t)i * DM + c4;
    const size_t sl = (size_t)S_LEN * DM;
    float4 s = make_float4(0.f, 0.f, 0.f, 0.f);
#pragma unroll
    for (int z = 0; z < 8; z++) {
        float4 p = *(const float4*)&g_part[(size_t)z * sl + off];
        s.x += p.x; s.y += p.y; s.z += p.z; s.w += p.w;
    }
    float4 bb = *(const float4*)&bo[c4];
    *(float4*)&out[off] = make_float4(s.x + bb.x, s.y + bb.y,
                                      s.z + bb.z, s.w + bb.w);
}

// ---------------- attention: block = (it,jg,h), covers up to 4 j-tiles ----
// p_ij = exp( TEMPC * (sumK_j - sum_d |Q_id - K_jd|) ); row-const terms cancel.
__global__ __launch_bounds__(256) void attn_kernel()
{
    const int it = c_it[blockIdx.x];
    const int jg = c_jg[blockIdx.x];
    const int h = blockIdx.y;

    __shared__ __align__(16) union SM {
        struct { float Kn[64][32]; float Vs[64][32]; float sK[64]; } a;
        struct { float red[4][64][33]; float redden[4][64]; } b;
    } sm;

    const int tid = threadIdx.x;
    const int ti = tid & 63;           // query row within tile
    const int tg = tid >> 6;           // 0..3, 4-way split over j

    const int ig = it * 64 + ti;
    uint64_t qp[16];
    {
        const ulonglong2* qg = (const ulonglong2*)&g_Q[ig * DM + h * DU];
#pragma unroll
        for (int c = 0; c < 8; c++) { ulonglong2 u = qg[c]; qp[2 * c] = u.x; qp[2 * c + 1] = u.y; }
    }

    uint64_t acc[16];
#pragma unroll
    for (int c = 0; c < 16; c++) acc[c] = 0;
    float den = 0.f;
    const uint64_t AMASK = 0x7FFFFFFF7FFFFFFFULL;

    auto jbody = [&](int jl) {
        const ulonglong2* kr = (const ulonglong2*)&sm.a.Kn[jl][0];
        uint64_t s0 = 0, s1 = 0;
#pragma unroll
        for (int c = 0; c < 8; c++) {
            ulonglong2 kc = kr[c];
            uint64_t t0 = f32x2_add(qp[2 * c], kc.x) & AMASK;       // FADD2 + 2xLOP3
            uint64_t t1 = f32x2_add(qp[2 * c + 1], kc.y) & AMASK;
            s0 = f32x2_add(s0, t0);
            s1 = f32x2_add(s1, t1);
        }
        float2 u0 = f32x2_unpack(s0), u1 = f32x2_unpack(s1);
        float s = (u0.x + u0.y) + (u1.x + u1.y);
        float p = fast_exp(TEMPC * (sm.a.sK[jl] - s));   // FMA pipe, no MUFU
        den += p;
        uint64_t pp = f32x2_pack(p, p);
        const ulonglong2* vr = (const ulonglong2*)&sm.a.Vs[jl][0];
#pragma unroll
        for (int c = 0; c < 8; c++) {
            ulonglong2 vc = vr[c];
            acc[2 * c]     = f32x2_fma(pp, vc.x, acc[2 * c]);       // FFMA2
            acc[2 * c + 1] = f32x2_fma(pp, vc.y, acc[2 * c + 1]);
        }
    };

    for (int sub = 0; sub < 4; sub++) {
        const int jt = jg * 4 + sub;
        if (jt > it) break;                 // uniform across block
        __syncthreads();                    // previous tile fully consumed
#pragma unroll
        for (int l = 0; l < 2; l++) {       // load K (negated) and V tiles
            int f = tid + l * 256;
            int r = f >> 3;
            int c4 = (f & 7) << 2;
            float4 kv = *(const float4*)&g_K[(jt * 64 + r) * DM + h * DU + c4];
            kv.x = -kv.x; kv.y = -kv.y; kv.z = -kv.z; kv.w = -kv.w;
            *(float4*)&sm.a.Kn[r][c4] = kv;
            *(float4*)&sm.a.Vs[r][c4] = *(const float4*)&g_V[(jt * 64 + r) * DM + h * DU + c4];
        }
        if (tid < 64) sm.a.sK[tid] = g_sumK[h * S_LEN + jt * 64 + tid];
        __syncthreads();

        if (jt != it) {
#pragma unroll 2
            for (int jj = 0; jj < 16; jj++) jbody((jj << 2) + tg);
        } else {
#pragma unroll 2
            for (int jj = 0; jj < 16; jj++) {
                int jl = (jj << 2) + tg;
                if (jl <= ti) jbody(jl);     // causal (diagonal tile only)
            }
        }
    }

    __syncthreads();   // all warps done with Kn/Vs before overlay write
#pragma unroll
    for (int c = 0; c < 16; c++) {
        float2 u = f32x2_unpack(acc[c]);
        sm.b.red[tg][ti][2 * c]     = u.x;
        sm.b.red[tg][ti][2 * c + 1] = u.y;
    }
    sm.b.redden[tg][ti] = den;
    __syncthreads();

    const int i2 = tid >> 2;       // 0..63
    const int dg = tid & 3;        // 8 d's each
    const int base = dg * 8;
    const int gi = it * 64 + i2;
    float outv[8];
#pragma unroll
    for (int dd = 0; dd < 8; dd++)
        outv[dd] = (sm.b.red[0][i2][base + dd] + sm.b.red[1][i2][base + dd]) +
                   (sm.b.red[2][i2][base + dd] + sm.b.red[3][i2][base + dd]);

    float* np = &g_pnum[(((size_t)jg * NH + h) * S_LEN + gi) * DU + base];
    *(float4*)&np[0] = make_float4(outv[0], outv[1], outv[2], outv[3]);
    *(float4*)&np[4] = make_float4(outv[4], outv[5], outv[6], outv[7]);
    if (dg == 0)
        g_pden[((size_t)jg * NH + h) * S_LEN + gi] =
            (sm.b.redden[0][i2] + sm.b.redden[1][i2]) +
            (sm.b.redden[2][i2] + sm.b.redden[3][i2]);
}

// ---------------- combine attn partials (<=4 j-groups), divide, write O ---
__global__ __launch_bounds__(256) void reduce_kernel()
{
    int idx = blockIdx.x * 256 + threadIdx.x;   // 65536, one float4 each
    int i = idx >> 6;              // sequence index
    int u = idx & 63;              // float4-unit within row
    int h = u >> 3;
    int d4 = (u & 7) << 2;
    int ng = (i >> 8) + 1;         // #valid j-groups = it/4 + 1
    const size_t sj = (size_t)NH * S_LEN * DU;
    const size_t sd = (size_t)NH * S_LEN;
    const float* pn = &g_pnum[((size_t)h * S_LEN + i) * DU + d4];
    const float* pd = &g_pden[(size_t)h * S_LEN + i];
    float4 n = make_float4(0.f, 0.f, 0.f, 0.f);
    float den = 0.f;
#pragma unroll 4
    for (int jg = 0; jg < ng; jg++) {
        float4 v = *(const float4*)(pn + (size_t)jg * sj);
        den += pd[(size_t)jg * sd];
        n.x += v.x; n.y += v.y; n.z += v.z; n.w += v.w;
    }
    float inv = 1.0f / den;
    *(float4*)&g_O[(size_t)i * DM + h * DU + d4] =
        make_float4(n.x * inv, n.y * inv, n.z * inv, n.w * inv);
}

// ---------------- launch ----------------
extern "C" void kernel_launch(void* const* d_in, const int* in_sizes, int n_in,
                              void* d_out, int out_size)
{
    const float* x  = (const float*)d_in[0];
    const float* Wq = (const float*)d_in[1];
    const float* bq = (const float*)d_in[2];
    const float* Wk = (const float*)d_in[3];
    const float* bk = (const float*)d_in[4];
    const float* Wv = (const float*)d_in[5];
    const float* bv = (const float*)d_in[6];
    const float* Wo = (const float*)d_in[7];
    const float* bo = (const float*)d_in[8];
    float* out = (float*)d_out;

    qkv_partial<<<dim3(32, 4, 12), 128>>>(x, Wq, Wk, Wv);
    combine_qkv<<<256, 256>>>(bq, bk, bv);
    attn_kernel<<<dim3(40, 8), 256>>>();
    reduce_kernel<<<256, 256>>>();
    proj_partial<<<dim3(32, 4, 8), 128>>>(Wo);
    combine_proj<<<256, 256>>>(bo, out);
}

// round 16
// speedup vs baseline: 1.4378x; 1.0689x over previous
#include <cuda_runtime.h>
#include <cstdint>

#define S_LEN 1024
#define DM 256
#define NH 8
#define DU 32
#define NT 16               // S_LEN / 64
#define NJG 4               // j-groups (4 j-tiles each)
#define TEMPC 0.078125f     // TEMP / (2*DU) = 5/64

// ---------------- scratch (no allocations allowed) ----------------
__device__ float g_Q[S_LEN * DM];
__device__ float g_K[S_LEN * DM];
__device__ float g_V[S_LEN * DM];
__device__ float g_sumK[NH * S_LEN];
__device__ float g_pnum[NJG * NH * S_LEN * DU];  // [jg][h][i][d]
__device__ float g_pden[NJG * NH * S_LEN];       // [jg][h][i]
__device__ float g_part[12 * S_LEN * DM];        // k-split GEMM partials

// (it, jg) enumeration for attn, sorted heaviest-first (w = #subtiles)
__device__ const unsigned char c_it[40] = {
    3,4,5,6,7,7,8,8,9,9,10,10,11,11,11,12,12,12,13,13,13,14,14,14,15,15,15,15,
    2,6,10,14,  1,5,9,13,  0,4,8,12};
__device__ const unsigned char c_jg[40] = {
    0,0,0,0,0,1,0,1,0,1,0,1,0,1,2,0,1,2,0,1,2,0,1,2,0,1,2,3,
    0,1,2,3,  0,1,2,3,  0,1,2,3};

// ---------------- packed f32x2 helpers ----------------
__device__ __forceinline__ uint64_t f32x2_add(uint64_t a, uint64_t b) {
    uint64_t d; asm("add.rn.f32x2 %0, %1, %2;" : "=l"(d) : "l"(a), "l"(b)); return d;
}
__device__ __forceinline__ uint64_t f32x2_fma(uint64_t a, uint64_t b, uint64_t c) {
    uint64_t d; asm("fma.rn.f32x2 %0, %1, %2, %3;" : "=l"(d) : "l"(a), "l"(b), "l"(c)); return d;
}
__device__ __forceinline__ uint64_t f32x2_pack(float x, float y) {
    uint64_t d; asm("mov.b64 %0, {%1, %2};" : "=l"(d) : "f"(x), "f"(y)); return d;
}
__device__ __forceinline__ float2 f32x2_unpack(uint64_t a) {
    float2 r; asm("mov.b64 {%0, %1}, %2;" : "=f"(r.x), "=f"(r.y) : "l"(a)); return r;
}

__device__ __forceinline__ float sigmoidf(float t) {
    return 1.0f / (1.0f + __expf(-t));
}

// ---------------- 32x64-tile partial GEMM, 128 threads, 4m x 4n ----------
__device__ __forceinline__ void gemm32p(const float* __restrict__ A,
                                        const float* __restrict__ W,
                                        float* __restrict__ C,
                                        int bm, int bn, int kstart, int kend)
{
    __shared__ __align__(16) float Ast[32][36];   // [k][m]
    __shared__ __align__(16) float Ws[32][64];    // [k][n]

    const int tid = threadIdx.x;      // 0..127
    const int tx = tid & 15;          // n = tx*4..+3
    const int ty = tid >> 4;          // m = ty*4..+3

    float c[4][4];
#pragma unroll
    for (int m = 0; m < 4; m++)
#pragma unroll
        for (int n = 0; n < 4; n++) c[m][n] = 0.f;

    for (int k0 = kstart; k0 < kend; k0 += 32) {
#pragma unroll
        for (int l = 0; l < 2; l++) {       // A tile 32m x 32k, transposed
            int f = tid + l * 128;
            int m = f >> 3;
            int kc = (f & 7) << 2;
            float4 v = *(const float4*)&A[(bm * 32 + m) * DM + k0 + kc];
            Ast[kc + 0][m] = v.x;
            Ast[kc + 1][m] = v.y;
            Ast[kc + 2][m] = v.z;
            Ast[kc + 3][m] = v.w;
        }
#pragma unroll
        for (int l = 0; l < 4; l++) {       // W tile 32k x 64n
            int f = tid + l * 128;
            int k = f >> 4;
            int nc = (f & 15) << 2;
            *(float4*)&Ws[k][nc] = *(const float4*)&W[(k0 + k) * DM + bn * 64 + nc];
        }
        __syncthreads();
#pragma unroll
        for (int k = 0; k < 32; k++) {
            float4 av = *(const float4*)&Ast[k][ty * 4];
            float4 wv = *(const float4*)&Ws[k][tx * 4];
            float am[4] = {av.x, av.y, av.z, av.w};
            float wn[4] = {wv.x, wv.y, wv.z, wv.w};
#pragma unroll
            for (int m = 0; m < 4; m++)
#pragma unroll
                for (int n = 0; n < 4; n++) c[m][n] += am[m] * wn[n];
        }
        __syncthreads();
    }

#pragma unroll
    for (int m = 0; m < 4; m++)
        *(float4*)&C[(bm * 32 + ty * 4 + m) * DM + bn * 64 + tx * 4] =
            make_float4(c[m][0], c[m][1], c[m][2], c[m][3]);
}

// qkv partial: z = tensor*4 + ksplit (k-split 4).  1536 blocks total.
__global__ __launch_bounds__(128) void qkv_partial(const float* __restrict__ x,
                                                   const float* __restrict__ Wq,
                                                   const float* __restrict__ Wk,
                                                   const float* __restrict__ Wv)
{
    int z = blockIdx.z;
    int t = z >> 2, ks = z & 3;
    const float* W = (t == 0) ? Wq : ((t == 1) ? Wk : Wv);
    gemm32p(x, W, g_part + (size_t)z * S_LEN * DM,
            blockIdx.x, blockIdx.y, ks * 64, ks * 64 + 64);
}

// combine qkv partials: bias + sigmoid(Q,K) + per-head sumK (shfl over 8 lanes)
__global__ __launch_bounds__(256) void combine_qkv(const float* __restrict__ bq,
                                                   const float* __restrict__ bk,
                                                   const float* __restrict__ bv)
{
    int idx = blockIdx.x * 256 + threadIdx.x;   // 65536, one float4 each
    int i = idx >> 6;
    int c4 = (idx & 63) << 2;
    size_t off = (size_t)i * DM + c4;
    const size_t sl = (size_t)S_LEN * DM;

    auto sum4 = [&](int base) {
        float4 a = *(const float4*)&g_part[(size_t)(base + 0) * sl + off];
        float4 b = *(const float4*)&g_part[(size_t)(base + 1) * sl + off];
        float4 c = *(const float4*)&g_part[(size_t)(base + 2) * sl + off];
        float4 d = *(const float4*)&g_part[(size_t)(base + 3) * sl + off];
        return make_float4((a.x + b.x) + (c.x + d.x), (a.y + b.y) + (c.y + d.y),
                           (a.z + b.z) + (c.z + d.z), (a.w + b.w) + (c.w + d.w));
    };

    // Q
    {
        float4 q = sum4(0);
        float4 bb = *(const float4*)&bq[c4];
        q.x = sigmoidf(q.x + bb.x);
        q.y = sigmoidf(q.y + bb.y);
        q.z = sigmoidf(q.z + bb.z);
        q.w = sigmoidf(q.w + bb.w);
        *(float4*)&g_Q[off] = q;
    }
    // K + sumK
    {
        float4 k = sum4(4);
        float4 bb = *(const float4*)&bk[c4];
        k.x = sigmoidf(k.x + bb.x);
        k.y = sigmoidf(k.y + bb.y);
        k.z = sigmoidf(k.z + bb.z);
        k.w = sigmoidf(k.w + bb.w);
        *(float4*)&g_K[off] = k;
        float s = (k.x + k.y) + (k.z + k.w);
        s += __shfl_xor_sync(0xFFFFFFFFu, s, 1);
        s += __shfl_xor_sync(0xFFFFFFFFu, s, 2);
        s += __shfl_xor_sync(0xFFFFFFFFu, s, 4);
        if ((threadIdx.x & 7) == 0) {
            int h = (idx & 63) >> 3;
            g_sumK[h * S_LEN + i] = s;
        }
    }
    // V
    {
        float4 v = sum4(8);
        float4 bb = *(const float4*)&bv[c4];
        *(float4*)&g_V[off] = make_float4(v.x + bb.x, v.y + bb.y,
                                          v.z + bb.z, v.w + bb.w);
    }
}

// ---------------- attention: block = (it,jg,h), covers up to 4 j-tiles ----
// p_ij = exp( TEMPC * (sumK_j - sum_d |Q_id - K_jd|) ); row-const terms cancel.
__global__ __launch_bounds__(256) void attn_kernel()
{
    const int it = c_it[blockIdx.x];
    const int jg = c_jg[blockIdx.x];
    const int h = blockIdx.y;

    __shared__ __align__(16) union SM {
        struct { float Kn[64][32]; float Vs[64][32]; float sK[64]; } a;
        struct { float red[4][64][33]; float redden[4][64]; } b;
    } sm;

    const int tid = threadIdx.x;
    const int ti = tid & 63;           // query row within tile
    const int tg = tid >> 6;           // 0..3, 4-way split over j

    const int ig = it * 64 + ti;
    uint64_t qp[16];
    {
        const ulonglong2* qg = (const ulonglong2*)&g_Q[ig * DM + h * DU];
#pragma unroll
        for (int c = 0; c < 8; c++) { ulonglong2 u = qg[c]; qp[2 * c] = u.x; qp[2 * c + 1] = u.y; }
    }

    uint64_t acc[16];
#pragma unroll
    for (int c = 0; c < 16; c++) acc[c] = 0;
    float den = 0.f;
    const uint64_t AMASK = 0x7FFFFFFF7FFFFFFFULL;

    auto jbody = [&](int jl) {
        const ulonglong2* kr = (const ulonglong2*)&sm.a.Kn[jl][0];
        uint64_t s0 = 0, s1 = 0;
#pragma unroll
        for (int c = 0; c < 8; c++) {
            ulonglong2 kc = kr[c];
            uint64_t t0 = f32x2_add(qp[2 * c], kc.x) & AMASK;       // FADD2 + 2xLOP3
            uint64_t t1 = f32x2_add(qp[2 * c + 1], kc.y) & AMASK;
            s0 = f32x2_add(s0, t0);
            s1 = f32x2_add(s1, t1);
        }
        float2 u0 = f32x2_unpack(s0), u1 = f32x2_unpack(s1);
        float s = (u0.x + u0.y) + (u1.x + u1.y);
        float p = __expf(TEMPC * (sm.a.sK[jl] - s));                // MUFU (cheap here)
        den += p;
        uint64_t pp = f32x2_pack(p, p);
        const ulonglong2* vr = (const ulonglong2*)&sm.a.Vs[jl][0];
#pragma unroll
        for (int c = 0; c < 8; c++) {
            ulonglong2 vc = vr[c];
            acc[2 * c]     = f32x2_fma(pp, vc.x, acc[2 * c]);       // FFMA2
            acc[2 * c + 1] = f32x2_fma(pp, vc.y, acc[2 * c + 1]);
        }
    };

    for (int sub = 0; sub < 4; sub++) {
        const int jt = jg * 4 + sub;
        if (jt > it) break;                 // uniform across block
        __syncthreads();                    // previous tile fully consumed
#pragma unroll
        for (int l = 0; l < 2; l++) {       // load K (negated) and V tiles
            int f = tid + l * 256;
            int r = f >> 3;
            int c4 = (f & 7) << 2;
            float4 kv = *(const float4*)&g_K[(jt * 64 + r) * DM + h * DU + c4];
            kv.x = -kv.x; kv.y = -kv.y; kv.z = -kv.z; kv.w = -kv.w;
            *(float4*)&sm.a.Kn[r][c4] = kv;
            *(float4*)&sm.a.Vs[r][c4] = *(const float4*)&g_V[(jt * 64 + r) * DM + h * DU + c4];
        }
        if (tid < 64) sm.a.sK[tid] = g_sumK[h * S_LEN + jt * 64 + tid];
        __syncthreads();

        if (jt != it) {
#pragma unroll 2
            for (int jj = 0; jj < 16; jj++) jbody((jj << 2) + tg);
        } else {
#pragma unroll 2
            for (int jj = 0; jj < 16; jj++) {
                int jl = (jj << 2) + tg;
                if (jl <= ti) jbody(jl);     // causal (diagonal tile only)
            }
        }
    }

    __syncthreads();   // all warps done with Kn/Vs before overlay write
#pragma unroll
    for (int c = 0; c < 16; c++) {
        float2 u = f32x2_unpack(acc[c]);
        sm.b.red[tg][ti][2 * c]     = u.x;
        sm.b.red[tg][ti][2 * c + 1] = u.y;
    }
    sm.b.redden[tg][ti] = den;
    __syncthreads();

    const int i2 = tid >> 2;       // 0..63
    const int dg = tid & 3;        // 8 d's each
    const int base = dg * 8;
    const int gi = it * 64 + i2;
    float outv[8];
#pragma unroll
    for (int dd = 0; dd < 8; dd++)
        outv[dd] = (sm.b.red[0][i2][base + dd] + sm.b.red[1][i2][base + dd]) +
                   (sm.b.red[2][i2][base + dd] + sm.b.red[3][i2][base + dd]);

    float* np = &g_pnum[(((size_t)jg * NH + h) * S_LEN + gi) * DU + base];
    *(float4*)&np[0] = make_float4(outv[0], outv[1], outv[2], outv[3]);
    *(float4*)&np[4] = make_float4(outv[4], outv[5], outv[6], outv[7]);
    if (dg == 0)
        g_pden[((size_t)jg * NH + h) * S_LEN + gi] =
            (sm.b.redden[0][i2] + sm.b.redden[1][i2]) +
            (sm.b.redden[2][i2] + sm.b.redden[3][i2]);
}

// ---------------- proj partial, FUSED with attn-partial reduction ----------
// Block (bm, bn, z):  z = head = k-slice (32 cols).  The A tile (rows
// bm*32..+32 of O, cols = head z) is reconstructed from g_pnum/g_pden in the
// prologue — no reduce kernel, no g_O roundtrip.  ng is block-uniform.
__global__ __launch_bounds__(128) void proj_partial(const float* __restrict__ Wo)
{
    const int bm = blockIdx.x, bn = blockIdx.y, z = blockIdx.z;  // z = head

    __shared__ __align__(16) float Ast[32][36];   // [d][m]
    __shared__ __align__(16) float Ws[32][64];    // [k][n]
    __shared__ float sinv[32];

    const int tid = threadIdx.x;      // 0..127
    const int tx = tid & 15;
    const int ty = tid >> 4;
    const int ng = (bm >> 3) + 1;     // #valid j-groups for these rows
    const size_t sj = (size_t)NH * S_LEN * DU;
    const size_t sd = (size_t)NH * S_LEN;

    // denominators (one per row)
    if (tid < 32) {
        const float* pd = &g_pden[(size_t)z * S_LEN + bm * 32 + tid];
        float den = 0.f;
        for (int jgi = 0; jgi < ng; jgi++) den += pd[(size_t)jgi * sd];
        sinv[tid] = 1.0f / den;
    }
    // W tile (32k x 64n), k = z*32 + wk
#pragma unroll
    for (int l = 0; l < 4; l++) {
        int f = tid + l * 128;
        int k = f >> 4;
        int nc = (f & 15) << 2;
        *(float4*)&Ws[k][nc] = *(const float4*)&Wo[(z * 32 + k) * DM + bn * 64 + nc];
    }
    __syncthreads();

    // numerators -> Ast[d][m] (each thread: one row m, 8 d's)
    {
        int m = tid >> 2;
        int d4 = (tid & 3) << 3;
        const float* pn = &g_pnum[((size_t)z * S_LEN + bm * 32 + m) * DU + d4];
        float4 n0 = make_float4(0.f, 0.f, 0.f, 0.f);
        float4 n1 = make_float4(0.f, 0.f, 0.f, 0.f);
        for (int jgi = 0; jgi < ng; jgi++) {
            float4 a = *(const float4*)(pn + (size_t)jgi * sj);
            float4 b = *(const float4*)(pn + (size_t)jgi * sj + 4);
            n0.x += a.x; n0.y += a.y; n0.z += a.z; n0.w += a.w;
            n1.x += b.x; n1.y += b.y; n1.z += b.z; n1.w += b.w;
        }
        float inv = sinv[m];
        Ast[d4 + 0][m] = n0.x * inv;
        Ast[d4 + 1][m] = n0.y * inv;
        Ast[d4 + 2][m] = n0.z * inv;
        Ast[d4 + 3][m] = n0.w * inv;
        Ast[d4 + 4][m] = n1.x * inv;
        Ast[d4 + 5][m] = n1.y * inv;
        Ast[d4 + 6][m] = n1.z * inv;
        Ast[d4 + 7][m] = n1.w * inv;
    }
    __syncthreads();

    float c[4][4];
#pragma unroll
    for (int m = 0; m < 4; m++)
#pragma unroll
        for (int n = 0; n < 4; n++) c[m][n] = 0.f;
#pragma unroll
    for (int k = 0; k < 32; k++) {
        float4 av = *(const float4*)&Ast[k][ty * 4];
        float4 wv = *(const float4*)&Ws[k][tx * 4];
        float am[4] = {av.x, av.y, av.z, av.w};
        float wn[4] = {wv.x, wv.y, wv.z, wv.w};
#pragma unroll
        for (int m = 0; m < 4; m++)
#pragma unroll
            for (int n = 0; n < 4; n++) c[m][n] += am[m] * wn[n];
    }

    float* C = g_part + (size_t)z * S_LEN * DM;
#pragma unroll
    for (int m = 0; m < 4; m++)
        *(float4*)&C[(size_t)(bm * 32 + ty * 4 + m) * DM + bn * 64 + tx * 4] =
            make_float4(c[m][0], c[m][1], c[m][2], c[m][3]);
}

// combine proj partials (8) + bias -> out
__global__ __launch_bounds__(256) void combine_proj(const float* __restrict__ bo,
                                                    float* __restrict__ out)
{
    int idx = blockIdx.x * 256 + threadIdx.x;   // 65536 float4s
    int i = idx >> 6;
    int c4 = (idx & 63) << 2;
    size_t off = (size_t)i * DM + c4;
    const size_t sl = (size_t)S_LEN * DM;
    float4 s = make_float4(0.f, 0.f, 0.f, 0.f);
#pragma unroll
    for (int z = 0; z < 8; z++) {
        float4 p = *(const float4*)&g_part[(size_t)z * sl + off];
        s.x += p.x; s.y += p.y; s.z += p.z; s.w += p.w;
    }
    float4 bb = *(const float4*)&bo[c4];
    *(float4*)&out[off] = make_float4(s.x + bb.x, s.y + bb.y,
                                      s.z + bb.z, s.w + bb.w);
}

// ---------------- launch ----------------
extern "C" void kernel_launch(void* const* d_in, const int* in_sizes, int n_in,
                              void* d_out, int out_size)
{
    const float* x  = (const float*)d_in[0];
    const float* Wq = (const float*)d_in[1];
    const float* bq = (const float*)d_in[2];
    const float* Wk = (const float*)d_in[3];
    const float* bk = (const float*)d_in[4];
    const float* Wv = (const float*)d_in[5];
    const float* bv = (const float*)d_in[6];
    const float* Wo = (const float*)d_in[7];
    const float* bo = (const float*)d_in[8];
    float* out = (float*)d_out;

    qkv_partial<<<dim3(32, 4, 12), 128>>>(x, Wq, Wk, Wv);
    combine_qkv<<<256, 256>>>(bq, bk, bv);
    attn_kernel<<<dim3(40, 8), 256>>>();
    proj_partial<<<dim3(32, 4, 8), 128>>>(Wo);
    combine_proj<<<256, 256>>>(bo, out);
}